// round 16
// baseline (speedup 1.0000x reference)
#include <cuda_runtime.h>
#include <cstdint>

// SubjectLayer: 256 SGEMMs (M=256,K=256,N=3000) via fp16 mma.sync m16n8k16.
// R16 = fp16 path of R15 at 4 warps/SMSP: CTA 128x128, 8 warps (4m x 2n),
// warp tile 32x64 (64 acc regs -> <=128 regs/thread -> 2 CTA/SM).
// A: fp16 fragment-ordered scratch (LDS.128). B: f32 smem rows, packed to
// f16x2 in regs (cvt.rn.f16x2.f32), half-granularity double buffer.
// 3-stage cp.async ring.

#define NSP 3000
#define CIN 256
#define NSUBJ 128
#define TM 128
#define TN 128
#define TK 32
#define NCHUNK 8
#define NSTAGE 3

#define A_WORDS 2048                    // 128x32 fp16 fragment-ordered per stage
#define BF_STRIDE 132                   // f32 B row stride (128+4)
#define B_WORDS (TK * BF_STRIDE)        // 4224
#define STAGE_WORDS (A_WORDS + B_WORDS) // 6272
#define SMEM_BYTES (NSTAGE * STAGE_WORDS * 4)   // 75264 (x2 CTA = 150KB)

// fp16 fragment-ordered weights: [s][c(8)][mt(16)][step(2)][lane(32)][reg(4)]
__device__ uint32_t g_wfrag[4 * 1024 * 1024];   // 16.8MB

__device__ __forceinline__ uint32_t packh(float lo, float hi) {
    uint32_t d;
    asm("cvt.rn.f16x2.f32 %0, %1, %2;" : "=r"(d) : "f"(hi), "f"(lo));
    return d;
}
__device__ __forceinline__ void cp16(uint32_t dst, const void* src) {
    asm volatile("cp.async.cg.shared.global [%0], [%1], 16;\n" :: "r"(dst), "l"(src));
}
__device__ __forceinline__ void cp16z(uint32_t dst, const void* src, int src_size) {
    asm volatile("cp.async.cg.shared.global [%0], [%1], 16, %2;\n"
                 :: "r"(dst), "l"(src), "r"(src_size));
}
__device__ __forceinline__ void mma_f16(float* d, const uint4 a,
                                        uint32_t b0, uint32_t b1) {
    asm volatile(
        "mma.sync.aligned.m16n8k16.row.col.f32.f16.f16.f32 "
        "{%0,%1,%2,%3}, {%4,%5,%6,%7}, {%8,%9}, {%0,%1,%2,%3};\n"
        : "+f"(d[0]), "+f"(d[1]), "+f"(d[2]), "+f"(d[3])
        : "r"(a.x), "r"(a.y), "r"(a.z), "r"(a.w), "r"(b0), "r"(b1));
}

// ---- Prologue: weights f32 -> fp16-packed fragment order (proven R15) ----
__global__ __launch_bounds__(256)
void wfrag_kernel(const float* __restrict__ w) {
    const int idx  = blockIdx.x * 256 + threadIdx.x;
    const int lane = idx & 31;
    const int step = (idx >> 5) & 1;
    const int mt   = (idx >> 6) & 15;
    const int c    = (idx >> 10) & 7;
    const int s    = idx >> 13;
    const int g = lane >> 2, t = lane & 3;
    const int m  = mt * 16 + g;
    const int k0 = c * 32 + step * 16 + 2 * t;
    const float* ws = w + (size_t)s * CIN * CIN;
    const float* r0 = ws + (size_t)m * CIN + k0;
    const float* r1 = ws + (size_t)(m + 8) * CIN + k0;
    uint4 r;
    r.x = packh(r0[0], r0[1]);
    r.y = packh(r1[0], r1[1]);
    r.z = packh(r0[8], r0[9]);
    r.w = packh(r1[8], r1[9]);
    reinterpret_cast<uint4*>(g_wfrag)[idx] = r;
}

// ---- Main GEMM ----
extern __shared__ uint32_t smem[];

__global__ __launch_bounds__(256, 2)
void subject_f16_kernel(const float* __restrict__ x,
                        const float* __restrict__ bias,
                        const int* __restrict__ subj,
                        float* __restrict__ out)
{
    const int b  = blockIdx.z;
    const int m0 = blockIdx.y * TM;
    const int n0 = blockIdx.x * TN;

    const int s = subj[b];
    const float* __restrict__ X  = x    + (size_t)b * CIN * NSP;
    const float* __restrict__ Bv = bias + (size_t)s * CIN;
    float* __restrict__ O        = out  + (size_t)b * CIN * NSP;

    const size_t wbase = (size_t)s * 128 + (m0 >> 4);

    const uint32_t sm_u32 = (uint32_t)__cvta_generic_to_shared(smem);

    const int tid    = threadIdx.x;
    const int wid    = tid >> 5;
    const int lane   = tid & 31;
    const int warp_m = wid & 3;        // 0..3 -> 32-row slabs
    const int warp_n = wid >> 2;       // 0..1 -> 64-col slabs
    const int group  = lane >> 2;
    const int tig    = lane & 3;
    const int bn     = warp_n * 64;
    const int mtl    = warp_m * 2;     // local m16-tile base

    float acc[2][8][4];
    #pragma unroll
    for (int mi = 0; mi < 2; mi++)
        #pragma unroll
        for (int ni = 0; ni < 8; ni++)
            #pragma unroll
            for (int r = 0; r < 4; r++)
                acc[mi][ni][r] = 0.0f;

    auto load_chunk = [&](int stage, int c) {
        const uint32_t sbase = sm_u32 + (uint32_t)(stage * STAGE_WORDS) * 4;
        // A: 8KB contiguous fp16 fragment block (512 uint4, 2/thread)
        const uint32_t* srcA = g_wfrag + (wbase + (size_t)c * 16) * 256;
        #pragma unroll
        for (int j = 0; j < 2; j++) {
            int u = j * 256 + tid;
            cp16(sbase + (uint32_t)u * 16, srcA + (size_t)u * 4);
        }
        // B: [32][128] f32 rows (stride 132), coalesced (1024 uint4, 4/thread)
        const int k0 = c * TK;
        const uint32_t bbase = sbase + A_WORDS * 4;
        #pragma unroll
        for (int j = 0; j < 4; j++) {
            int u = j * 256 + tid;
            int k  = u >> 5;
            int n4 = (u & 31) << 2;
            int gn = n0 + n4;
            int ok = (gn < NSP);
            cp16z(bbase + (uint32_t)(k * BF_STRIDE + n4) * 4,
                  X + (size_t)(k0 + k) * NSP + (ok ? gn : 0),
                  ok ? 16 : 0);
        }
        asm volatile("cp.async.commit_group;\n");
    };

    auto compute_chunk = [&](int stage) {
        const uint32_t* A = smem + stage * STAGE_WORDS;
        const float* Bf = reinterpret_cast<const float*>(A + A_WORDS);
        // B fragment half: 4 ni (8 regs).  sidx = step*2 + h.
        uint32_t bw[2][8];
        auto load_bhalf = [&](uint32_t* d, int sidx) {
            const int step = sidx >> 1;
            const int h    = sidx & 1;
            const int r0 = (step * 16 + 2 * tig) * BF_STRIDE + bn + h * 32 + group;
            #pragma unroll
            for (int j = 0; j < 4; j++) {
                float f0 = Bf[r0 + j * 8];
                float f1 = Bf[r0 + BF_STRIDE + j * 8];
                float f2 = Bf[r0 + 8 * BF_STRIDE + j * 8];
                float f3 = Bf[r0 + 9 * BF_STRIDE + j * 8];
                d[2 * j]     = packh(f0, f1);
                d[2 * j + 1] = packh(f2, f3);
            }
        };
        load_bhalf(bw[0], 0);
        #pragma unroll
        for (int step = 0; step < 2; step++) {
            uint4 a0 = *reinterpret_cast<const uint4*>(
                &A[(uint32_t)(((mtl)     * 2 + step) * 128 + lane * 4)]);
            uint4 a1 = *reinterpret_cast<const uint4*>(
                &A[(uint32_t)(((mtl + 1) * 2 + step) * 128 + lane * 4)]);
            #pragma unroll
            for (int h = 0; h < 2; h++) {
                const int sidx = step * 2 + h;
                if (sidx < 3) load_bhalf(bw[(sidx + 1) & 1], sidx + 1);
                const uint32_t* cur = bw[sidx & 1];
                #pragma unroll
                for (int j = 0; j < 4; j++) {
                    const int ni = h * 4 + j;
                    mma_f16(acc[0][ni], a0, cur[2 * j], cur[2 * j + 1]);
                    mma_f16(acc[1][ni], a1, cur[2 * j], cur[2 * j + 1]);
                }
            }
        }
    };

    // Prologue: stage chunks 0 and 1.
    load_chunk(0, 0);
    load_chunk(1, 1);

    #pragma unroll 1
    for (int c = 0; c < NCHUNK; c++) {
        if (c + 1 < NCHUNK) {
            asm volatile("cp.async.wait_group 1;\n");
        } else {
            asm volatile("cp.async.wait_group 0;\n");
        }
        __syncthreads();
        if (c + 2 < NCHUNK) load_chunk((c + 2) % NSTAGE, c + 2);
        compute_chunk(c % NSTAGE);
    }

    // Epilogue: bias add + float2 stores.
    const int am = warp_m * 32;
    #pragma unroll
    for (int mi = 0; mi < 2; mi++) {
        const int mrow = m0 + am + mi * 16 + group;
        const float bv0 = Bv[mrow];
        const float bv1 = Bv[mrow + 8];
        #pragma unroll
        for (int ni = 0; ni < 8; ni++) {
            const int n = n0 + bn + ni * 8 + tig * 2;
            if (n < NSP) {
                float2 v0 = make_float2(acc[mi][ni][0] + bv0, acc[mi][ni][1] + bv0);
                *reinterpret_cast<float2*>(&O[(size_t)mrow * NSP + n]) = v0;
                float2 v1 = make_float2(acc[mi][ni][2] + bv1, acc[mi][ni][3] + bv1);
                *reinterpret_cast<float2*>(&O[(size_t)(mrow + 8) * NSP + n]) = v1;
            }
        }
    }
}

extern "C" void kernel_launch(void* const* d_in, const int* in_sizes, int n_in,
                              void* d_out, int out_size) {
    const float* x      = (const float*)d_in[0];
    const float* weight = (const float*)d_in[1];
    const float* bias   = (const float*)d_in[2];
    const int*   subj   = (const int*)d_in[3];
    float*       out    = (float*)d_out;

    // 1) weights -> fp16-packed fragment-ordered scratch
    wfrag_kernel<<<4096, 256>>>(weight);

    // 2) main GEMM
    cudaFuncSetAttribute(subject_f16_kernel,
                         cudaFuncAttributeMaxDynamicSharedMemorySize, SMEM_BYTES);
    dim3 block(256);
    dim3 grid((NSP + TN - 1) / TN, CIN / TM, 256);   // (24, 2, 256)
    subject_f16_kernel<<<grid, block, SMEM_BYTES>>>(x, bias, subj, out);
}

// round 17
// speedup vs baseline: 1.0852x; 1.0852x over previous
#include <cuda_runtime.h>
#include <cstdint>

// SubjectLayer: 256 SGEMMs (M=256,K=256,N=3000) via fp16 mma.sync m16n8k16.
// R17 = R15 (best, 442us: CTA 128x128, 4 warps 64x64, fp16 frag-ordered A
// scratch, f32 B smem + reg packh, 2 CTA/SM) with TK 32->64: 4 chunks instead
// of 8 -> half the barriers and post-barrier ramps. Ring-2 cp.async (load c+1
// issued before compute c; wait covers a full 2048-cyc compute phase).

#define NSP 3000
#define CIN 256
#define NSUBJ 128
#define TM 128
#define TN 128
#define TK 64
#define NCHUNK 4
#define NSTAGE 2

#define A_WORDS 4096                    // 128x64 fp16 fragments per stage (16KB)
#define BF_STRIDE 132                   // f32 B row stride (128+4)
#define B_WORDS (TK * BF_STRIDE)        // 8448
#define STAGE_WORDS (A_WORDS + B_WORDS) // 12544
#define SMEM_BYTES (NSTAGE * STAGE_WORDS * 4)   // 100352 (x2 CTA = 196KB <= 228KB)

// fp16 fragment-ordered weights: [s][c32(8)][mt(16)][step(2)][lane(32)][reg(4)]
// (c32 = 32-wide k block; a TK=64 chunk consumes blocks 2c and 2c+1)
__device__ uint32_t g_wfrag[4 * 1024 * 1024];   // 16.8MB

__device__ __forceinline__ uint32_t packh(float lo, float hi) {
    uint32_t d;
    asm("cvt.rn.f16x2.f32 %0, %1, %2;" : "=r"(d) : "f"(hi), "f"(lo));
    return d;
}
__device__ __forceinline__ void cp16(uint32_t dst, const void* src) {
    asm volatile("cp.async.cg.shared.global [%0], [%1], 16;\n" :: "r"(dst), "l"(src));
}
__device__ __forceinline__ void cp16z(uint32_t dst, const void* src, int src_size) {
    asm volatile("cp.async.cg.shared.global [%0], [%1], 16, %2;\n"
                 :: "r"(dst), "l"(src), "r"(src_size));
}
__device__ __forceinline__ void mma_f16(float* d, const uint4 a,
                                        uint32_t b0, uint32_t b1) {
    asm volatile(
        "mma.sync.aligned.m16n8k16.row.col.f32.f16.f16.f32 "
        "{%0,%1,%2,%3}, {%4,%5,%6,%7}, {%8,%9}, {%0,%1,%2,%3};\n"
        : "+f"(d[0]), "+f"(d[1]), "+f"(d[2]), "+f"(d[3])
        : "r"(a.x), "r"(a.y), "r"(a.z), "r"(a.w), "r"(b0), "r"(b1));
}

// ---- Prologue: weights f32 -> fp16-packed fragment order (proven R15) ----
__global__ __launch_bounds__(256)
void wfrag_kernel(const float* __restrict__ w) {
    const int idx  = blockIdx.x * 256 + threadIdx.x;
    const int lane = idx & 31;
    const int step = (idx >> 5) & 1;
    const int mt   = (idx >> 6) & 15;
    const int c    = (idx >> 10) & 7;
    const int s    = idx >> 13;
    const int g = lane >> 2, t = lane & 3;
    const int m  = mt * 16 + g;
    const int k0 = c * 32 + step * 16 + 2 * t;
    const float* ws = w + (size_t)s * CIN * CIN;
    const float* r0 = ws + (size_t)m * CIN + k0;
    const float* r1 = ws + (size_t)(m + 8) * CIN + k0;
    uint4 r;
    r.x = packh(r0[0], r0[1]);
    r.y = packh(r1[0], r1[1]);
    r.z = packh(r0[8], r0[9]);
    r.w = packh(r1[8], r1[9]);
    reinterpret_cast<uint4*>(g_wfrag)[idx] = r;
}

// ---- Main GEMM ----
extern __shared__ uint32_t smem[];

__global__ __launch_bounds__(128, 2)
void subject_f16_kernel(const float* __restrict__ x,
                        const float* __restrict__ bias,
                        const int* __restrict__ subj,
                        float* __restrict__ out)
{
    const int b  = blockIdx.z;
    const int m0 = blockIdx.y * TM;
    const int n0 = blockIdx.x * TN;

    const int s = subj[b];
    const float* __restrict__ X  = x    + (size_t)b * CIN * NSP;
    const float* __restrict__ Bv = bias + (size_t)s * CIN;
    float* __restrict__ O        = out  + (size_t)b * CIN * NSP;

    // word offset of (s, c32-block, local m-half) A block: (wbase + c32*16)*256
    const size_t wbase = (size_t)s * 128 + (m0 >> 4);

    const uint32_t sm_u32 = (uint32_t)__cvta_generic_to_shared(smem);

    const int tid    = threadIdx.x;
    const int wid    = tid >> 5;
    const int lane   = tid & 31;
    const int warp_m = wid & 1;
    const int warp_n = wid >> 1;
    const int group  = lane >> 2;
    const int tig    = lane & 3;
    const int bn     = warp_n * 64;
    const int mtl    = warp_m * 4;     // local m16-tile base (0 or 4)

    float acc[4][8][4];
    #pragma unroll
    for (int mi = 0; mi < 4; mi++)
        #pragma unroll
        for (int ni = 0; ni < 8; ni++)
            #pragma unroll
            for (int r = 0; r < 4; r++)
                acc[mi][ni][r] = 0.0f;

    auto load_chunk = [&](int stage, int c) {
        const uint32_t sbase = sm_u32 + (uint32_t)(stage * STAGE_WORDS) * 4;
        // A: two adjacent 8KB 32-k blocks (512 uint4 each, 4/thread each)
        const uint32_t* srcA0 = g_wfrag + (wbase + (size_t)(2 * c) * 16) * 256;
        const uint32_t* srcA1 = g_wfrag + (wbase + (size_t)(2 * c + 1) * 16) * 256;
        #pragma unroll
        for (int j = 0; j < 4; j++) {
            int u = j * 128 + tid;
            cp16(sbase + (uint32_t)u * 16, srcA0 + (size_t)u * 4);
        }
        #pragma unroll
        for (int j = 0; j < 4; j++) {
            int u = j * 128 + tid;
            cp16(sbase + 8192 + (uint32_t)u * 16, srcA1 + (size_t)u * 4);
        }
        // B: [64][128] f32 rows (stride 132), coalesced (2048 uint4, 16/thread)
        const int k0 = c * TK;
        const uint32_t bbase = sbase + A_WORDS * 4;
        #pragma unroll
        for (int j = 0; j < 16; j++) {
            int u = j * 128 + tid;
            int k  = u >> 5;            // 0..63
            int n4 = (u & 31) << 2;
            int gn = n0 + n4;
            int ok = (gn < NSP);
            cp16z(bbase + (uint32_t)(k * BF_STRIDE + n4) * 4,
                  X + (size_t)(k0 + k) * NSP + (ok ? gn : 0),
                  ok ? 16 : 0);
        }
        asm volatile("cp.async.commit_group;\n");
    };

    auto compute_chunk = [&](int stage) {
        const uint32_t* A = smem + stage * STAGE_WORDS;
        const float* Bf = reinterpret_cast<const float*>(A + A_WORDS);
        uint32_t bw[2][16];
        auto load_bfrags = [&](uint32_t* d, int st) {     // st = 0..3 (16 k's each)
            const int r0 = (st * 16 + 2 * tig) * BF_STRIDE + bn + group;
            #pragma unroll
            for (int ni = 0; ni < 8; ni++) {
                float f0 = Bf[r0 + ni * 8];
                float f1 = Bf[r0 + BF_STRIDE + ni * 8];
                float f2 = Bf[r0 + 8 * BF_STRIDE + ni * 8];
                float f3 = Bf[r0 + 9 * BF_STRIDE + ni * 8];
                d[ni * 2]     = packh(f0, f1);
                d[ni * 2 + 1] = packh(f2, f3);
            }
        };
        load_bfrags(bw[0], 0);
        #pragma unroll
        for (int st = 0; st < 4; st++) {
            if (st < 3) load_bfrags(bw[(st + 1) & 1], st + 1);
            const uint32_t* bcur = bw[st & 1];
            uint4 a[4];
            #pragma unroll
            for (int mi = 0; mi < 4; mi++)
                a[mi] = *reinterpret_cast<const uint4*>(
                    &A[(uint32_t)((st >> 1) * 2048
                                  + ((mtl + mi) * 2 + (st & 1)) * 128 + lane * 4)]);
            #pragma unroll
            for (int ni = 0; ni < 8; ni++) {
                #pragma unroll
                for (int mi = 0; mi < 4; mi++)
                    mma_f16(acc[mi][ni], a[mi], bcur[ni * 2], bcur[ni * 2 + 1]);
            }
        }
    };

    // Prologue: stage chunk 0.
    load_chunk(0, 0);
    asm volatile("cp.async.wait_group 0;\n");
    __syncthreads();

    #pragma unroll 1
    for (int c = 0; c < NCHUNK; c++) {
        const int buf = c & 1;
        if (c + 1 < NCHUNK) {
            load_chunk(buf ^ 1, c + 1);     // overlaps compute below
            compute_chunk(buf);
            asm volatile("cp.async.wait_group 0;\n");
            __syncthreads();
        } else {
            compute_chunk(buf);
        }
    }

    // Epilogue: bias add + float2 stores.
    const int am = warp_m * 64;
    #pragma unroll
    for (int mi = 0; mi < 4; mi++) {
        const int mrow = m0 + am + mi * 16 + group;
        const float bv0 = Bv[mrow];
        const float bv1 = Bv[mrow + 8];
        #pragma unroll
        for (int ni = 0; ni < 8; ni++) {
            const int n = n0 + bn + ni * 8 + tig * 2;
            if (n < NSP) {
                float2 v0 = make_float2(acc[mi][ni][0] + bv0, acc[mi][ni][1] + bv0);
                *reinterpret_cast<float2*>(&O[(size_t)mrow * NSP + n]) = v0;
                float2 v1 = make_float2(acc[mi][ni][2] + bv1, acc[mi][ni][3] + bv1);
                *reinterpret_cast<float2*>(&O[(size_t)(mrow + 8) * NSP + n]) = v1;
            }
        }
    }
}

extern "C" void kernel_launch(void* const* d_in, const int* in_sizes, int n_in,
                              void* d_out, int out_size) {
    const float* x      = (const float*)d_in[0];
    const float* weight = (const float*)d_in[1];
    const float* bias   = (const float*)d_in[2];
    const int*   subj   = (const int*)d_in[3];
    float*       out    = (float*)d_out;

    // 1) weights -> fp16-packed fragment-ordered scratch
    wfrag_kernel<<<4096, 256>>>(weight);

    // 2) main GEMM
    cudaFuncSetAttribute(subject_f16_kernel,
                         cudaFuncAttributeMaxDynamicSharedMemorySize, SMEM_BYTES);
    dim3 block(128);
    dim3 grid((NSP + TN - 1) / TN, CIN / TM, 256);   // (24, 2, 256)
    subject_f16_kernel<<<grid, block, SMEM_BYTES>>>(x, bias, subj, out);
}